// round 6
// baseline (speedup 1.0000x reference)
#include <cuda_runtime.h>

// Conv2D 7x7 VALID, 4096x4096 fp32 -> 4090x4090, + scalar bias.
// v4 (resubmit after infra failure): FFMA2 with persistent pre-packed weight
// pairs + aligned-pair window.
//   - 49 weights pre-packed (w,w) into u64 regs ONCE; launch_bounds(128,3)
//     gives ptxas room to keep them hoisted (v3b rematerialized them in-loop
//     under the occ-4 reg cap -> alu pipe 39%).
//   - Window read as ulonglong2/u64: even pairs come out of LDS.128 for free;
//     only 4 odd-offset pairs per row need packing.
//   - 784 FFMA2 + ~11 window instrs/row; bitwise-identical numerics.

#define KH 7
#define KW 7
#define H_IN 4096
#define W_IN 4096
#define H_OUT 4090
#define W_OUT 4090

#define TILE_W 128
#define TILE_H 32
#define OX 4
#define OY 8
#define IN_H (TILE_H + KH - 1)   // 38
#define PITCH 136                // row stride 544B (mult of 16) -> 16B-aligned rows

typedef unsigned long long u64;

__device__ __forceinline__ u64 pack2(float lo, float hi) {
    u64 r;
    asm("mov.b64 %0, {%1, %2};" : "=l"(r) : "f"(lo), "f"(hi));
    return r;
}
__device__ __forceinline__ void unpack2(u64 p, float& lo, float& hi) {
    asm("mov.b64 {%0, %1}, %2;" : "=f"(lo), "=f"(hi) : "l"(p));
}
__device__ __forceinline__ void fma2(u64& d, u64 a, u64 b) {
    asm("fma.rn.f32x2 %0, %1, %2, %0;" : "+l"(d) : "l"(a), "l"(b));
}
__device__ __forceinline__ u64 add2(u64 a, u64 b) {
    u64 r;
    asm("add.rn.f32x2 %0, %1, %2;" : "=l"(r) : "l"(a), "l"(b));
    return r;
}

__global__ __launch_bounds__(128, 3)
void conv7x7_v4(const float* __restrict__ X,
                const float* __restrict__ Wt,
                const float* __restrict__ bias,
                float* __restrict__ out) {
    __shared__ float tile[IN_H * PITCH];

    const int tid = threadIdx.x;
    const int tx  = tid & 31;
    const int ty  = tid >> 5;
    const int x0  = blockIdx.x * TILE_W;
    const int y0  = blockIdx.y * TILE_H;

    // ---- weights pre-packed (w,w), persistent in regs; bias ----
    u64 w2[KH * KW];
#pragma unroll
    for (int i = 0; i < KH * KW; i++) {
        const float wv = __ldg(&Wt[i]);
        w2[i] = pack2(wv, wv);
    }
    const float b = __ldg(&bias[0]);

    // ---- stage input tile (38 x 136), float4 coalesced ----
    const bool interior_in = (x0 + PITCH <= W_IN) && (y0 + IN_H <= H_IN);
    if (interior_in) {
#pragma unroll
        for (int i = tid; i < IN_H * (PITCH / 4); i += 128) {
            const int r  = i / (PITCH / 4);
            const int c4 = i % (PITCH / 4);
            *reinterpret_cast<float4*>(&tile[r * PITCH + c4 * 4]) =
                *reinterpret_cast<const float4*>(
                    X + (size_t)(y0 + r) * W_IN + x0 + c4 * 4);
        }
    } else {
        for (int i = tid; i < IN_H * (PITCH / 4); i += 128) {
            const int r  = i / (PITCH / 4);
            const int c4 = i % (PITCH / 4);
            const int gy = y0 + r;
            const int gx = x0 + c4 * 4;
            float4 val = make_float4(0.f, 0.f, 0.f, 0.f);
            // gx multiple of 4, W_IN % 4 == 0 -> float4 never straddles row end
            if (gy < H_IN && gx < W_IN) {
                val = *reinterpret_cast<const float4*>(
                    X + (size_t)gy * W_IN + gx);
            }
            *reinterpret_cast<float4*>(&tile[r * PITCH + c4 * 4]) = val;
        }
    }
    __syncthreads();

    // ---- compute: 2 f32x2 pairs x 8 rows per thread ----
    u64 acc2[OY][2];
#pragma unroll
    for (int oy = 0; oy < OY; oy++) {
        acc2[oy][0] = 0ull;
        acc2[oy][1] = 0ull;
    }

    const int cbase = tx * OX;   // even, and tile rows are 16B-aligned
    const int rbase = ty * OY;

#pragma unroll
    for (int j = 0; j < OY + KH - 1; j++) {        // 14 input rows
        const float* rowp = &tile[(rbase + j) * PITCH + cbase];
        // Even-aligned pairs straight from wide LDS (no packing needed):
        ulonglong2 A0 = *reinterpret_cast<const ulonglong2*>(rowp);     // (v0,v1),(v2,v3)
        ulonglong2 A1 = *reinterpret_cast<const ulonglong2*>(rowp + 4); // (v4,v5),(v6,v7)
        u64        A2 = *reinterpret_cast<const u64*>(rowp + 8);        // (v8,v9)

        u64 P[9];
        P[0] = A0.x;  P[2] = A0.y;  P[4] = A1.x;  P[6] = A1.y;  P[8] = A2;

        // Odd-offset pairs: 4 packs from unpacked halves.
        float vd, v1, v2c, v3, v4, v5, v6, v7, v8;
        unpack2(A0.x, vd, v1);
        unpack2(A0.y, v2c, v3);
        unpack2(A1.x, v4, v5);
        unpack2(A1.y, v6, v7);
        unpack2(A2,  v8, vd);
        P[1] = pack2(v1, v2c);
        P[3] = pack2(v3, v4);
        P[5] = pack2(v5, v6);
        P[7] = pack2(v7, v8);

#pragma unroll
        for (int ky = 0; ky < KH; ky++) {
            const int oy = j - ky;
            if (oy >= 0 && oy < OY) {
#pragma unroll
                for (int kx = 0; kx < KW; kx++) {
                    fma2(acc2[oy][0], P[kx],     w2[ky * KW + kx]);
                    fma2(acc2[oy][1], P[kx + 2], w2[ky * KW + kx]);
                }
            }
        }
    }

    // ---- store (packed bias add, 8-byte stores on interior) ----
    const int xo  = x0 + cbase;
    const int yo0 = y0 + rbase;
    const u64 b2  = pack2(b, b);
    const bool interior_out = (x0 + TILE_W <= W_OUT) && (y0 + TILE_H <= H_OUT);
    if (interior_out) {
#pragma unroll
        for (int oy = 0; oy < OY; oy++) {
            float* op = out + (size_t)(yo0 + oy) * W_OUT + xo;
            u64 r0 = add2(acc2[oy][0], b2);
            u64 r1 = add2(acc2[oy][1], b2);
            *reinterpret_cast<u64*>(op + 0) = r0;   // (yo*W_OUT+xo) even -> 8B aligned
            *reinterpret_cast<u64*>(op + 2) = r1;
        }
    } else {
#pragma unroll
        for (int oy = 0; oy < OY; oy++) {
            const int yo = yo0 + oy;
            if (yo < H_OUT) {
                float r[OX];
                unpack2(acc2[oy][0], r[0], r[1]);
                unpack2(acc2[oy][1], r[2], r[3]);
#pragma unroll
                for (int ox = 0; ox < OX; ox++) {
                    const int xc = xo + ox;
                    if (xc < W_OUT) {
                        out[(size_t)yo * W_OUT + xc] = r[ox] + b;
                    }
                }
            }
        }
    }
}

extern "C" void kernel_launch(void* const* d_in, const int* in_sizes, int n_in,
                              void* d_out, int out_size) {
    const float* X    = (const float*)d_in[0];
    const float* Wt   = (const float*)d_in[1];
    const float* bias = (const float*)d_in[2];
    float* out = (float*)d_out;

    dim3 grid((W_OUT + TILE_W - 1) / TILE_W,   // 32
              (H_OUT + TILE_H - 1) / TILE_H);  // 128
    dim3 block(128);
    conv7x7_v4<<<grid, block>>>(X, Wt, bias, out);
}